// round 10
// baseline (speedup 1.0000x reference)
#include <cuda_runtime.h>

// Find_Ring_Bonds: B=16384 molecules, A=80 atoms, D=4 neighbors, R=10 rings, S=8.
// edges: [B, A, D] float32 (integer-valued, -1 = null neighbor)
// rings: [B, R, S] int32 (-1 = padding)
// out:   [B, A, D] float32 (1.0 iff bond (a, e[a][d]) lies in some ring)
//
// Atomic-free formulation. Ring entries are packed to bytes (-1 -> 0xFF,
// which can never equal an atom id 0..79). Each atom thread computes its
// 10-bit ring membership mask with __vcmpeq4 SIMD byte compares against the
// packed ring table (2 words per ring), then bond (a,e) is a ring bond iff
// (mask[a] & mask[e]) != 0 and e != -1. This replaces the former shared
// atomicOr scatter (~64 LSU-cycles/warp, the R7 bottleneck) with fixed-lat
// ALU work on otherwise-idle pipes.

static constexpr int A = 80;
static constexpr int D = 4;
static constexpr int R = 10;
static constexpr int S = 8;
static constexpr int PACK_WORDS = (R * S) / 4;        // 20 packed words / molecule
static constexpr int MOLS_PER_BLOCK = 4;
static constexpr int THREADS = MOLS_PER_BLOCK * A;    // 320

__global__ __launch_bounds__(THREADS, 6)
void find_ring_bonds_kernel(const float* __restrict__ edges,
                            const int*   __restrict__ rings,
                            float*       __restrict__ out)
{
    __shared__ unsigned int ringpack[MOLS_PER_BLOCK][PACK_WORDS];
    __shared__ unsigned int atom_rings[MOLS_PER_BLOCK][A];

    const int tid = threadIdx.x;
    const int m = tid / A;          // local molecule 0..3
    const int a = tid % A;          // atom index 0..79
    const long mol = (long)blockIdx.x * MOLS_PER_BLOCK + m;

    // Front-batch the edges load; it resolves during the barrier-separated
    // shared-memory phases below.
    const float4 e4 = __ldcs(reinterpret_cast<const float4*>(edges) + mol * A + a);

    // Phase 1: byte-pack ring entries into shared. 20 threads per molecule,
    // each loads 4 consecutive int32 entries (int4, coalesced) and packs the
    // low bytes (-1 -> 0xFF).
    if (a < PACK_WORDS) {
        const int4 rv = __ldcs(reinterpret_cast<const int4*>(rings) + mol * PACK_WORDS + a);
        const unsigned int p = ( (unsigned)rv.x & 0xFFu)
                             | (((unsigned)rv.y & 0xFFu) << 8)
                             | (((unsigned)rv.z & 0xFFu) << 16)
                             | (((unsigned)rv.w & 0xFFu) << 24);
        ringpack[m][a] = p;
    }
    __syncthreads();

    // Phase 2: each atom thread computes its 10-bit ring mask via SIMD byte
    // compares. All shared loads are warp-uniform per molecule (broadcast).
    {
        const unsigned int aa = (unsigned)a * 0x01010101u;   // byte-splat of atom id
        unsigned int mask = 0u;
        #pragma unroll
        for (int r = 0; r < R; r++) {
            const unsigned int w0 = ringpack[m][2 * r + 0];
            const unsigned int w1 = ringpack[m][2 * r + 1];
            const unsigned int eq = __vcmpeq4(w0, aa) | __vcmpeq4(w1, aa);
            mask |= (eq != 0u ? 1u : 0u) << r;
        }
        atom_rings[m][a] = mask;
    }
    __syncthreads();

    // Phase 3: resolve 4 neighbor slots per atom via shared gathers.
    const unsigned int my_rings = atom_rings[m][a];

    const int e0 = (int)e4.x;
    const int e1 = (int)e4.y;
    const int e2 = (int)e4.z;
    const int e3 = (int)e4.w;

    float4 o;
    o.x = (e0 >= 0 && (my_rings & atom_rings[m][e0])) ? 1.0f : 0.0f;
    o.y = (e1 >= 0 && (my_rings & atom_rings[m][e1])) ? 1.0f : 0.0f;
    o.z = (e2 >= 0 && (my_rings & atom_rings[m][e2])) ? 1.0f : 0.0f;
    o.w = (e3 >= 0 && (my_rings & atom_rings[m][e3])) ? 1.0f : 0.0f;

    __stwt(reinterpret_cast<float4*>(out) + mol * A + a, o);
}

extern "C" void kernel_launch(void* const* d_in, const int* in_sizes, int n_in,
                              void* d_out, int out_size)
{
    const float* edges = (const float*)d_in[0];   // [B, A, D] float32
    const int*   rings = (const int*)d_in[1];     // [B, R, S] int32
    float* out = (float*)d_out;                   // [B, A, D, 1] float32

    const int batch = out_size / (A * D);         // 16384
    const int grid = (batch + MOLS_PER_BLOCK - 1) / MOLS_PER_BLOCK;

    find_ring_bonds_kernel<<<grid, THREADS>>>(edges, rings, out);
}

// round 12
// speedup vs baseline: 1.5731x; 1.5731x over previous
#include <cuda_runtime.h>

// Find_Ring_Bonds: B=16384 molecules, A=80 atoms, D=4 neighbors, R=10 rings, S=8.
// edges: [B, A, D] float32 (integer-valued, -1 = null neighbor)
// rings: [B, R, S] int32 (-1 = padding)
// out:   [B, A, D] float32 (1.0 iff bond (a, e[a][d]) lies in some ring)
//
// Atomic-free scatter. Each atom gets a 16-byte shared staging row, one flag
// byte per ring. Ring entry (r, s) with atom v does a plain byte store
// staging[v].byte[r] = 1 — shared byte stores have per-lane byte enables, so
// there is no RMW hazard (same-byte writers store the same value). Each atom
// thread then reads its row with one LDS.128 and collapses the 10 flag bytes
// into a 10-bit mask via movemask multiplies (bit order is a fixed permutation
// of rings — irrelevant since masks are only ANDed against each other).
// Bond (a,e) is a ring bond iff (mask[a] & mask[e]) != 0 and e != -1.
//
// This keeps the O(80)-ops-per-molecule scatter algorithm (the R10 gather
// formulation was 20x more work) while replacing ATOMS (~2 cyc/lane, the R7
// LSU binder) with cheap byte STS.

static constexpr int A = 80;
static constexpr int D = 4;
static constexpr int R = 10;
static constexpr int S = 8;
static constexpr int MOLS_PER_BLOCK = 4;
static constexpr int THREADS = MOLS_PER_BLOCK * A;    // 320

__global__ __launch_bounds__(THREADS, 6)
void find_ring_bonds_kernel(const float* __restrict__ edges,
                            const int*   __restrict__ rings,
                            float*       __restrict__ out)
{
    // staging[m][a]: 16 flag bytes (rings 0..9 in bytes 0..9, rest pad)
    __shared__ uint4        staging[MOLS_PER_BLOCK][A];
    __shared__ unsigned int atom_rings[MOLS_PER_BLOCK][A];

    const int tid = threadIdx.x;
    const int m = tid / A;          // local molecule 0..3
    const int a = tid % A;          // atom index == ring-entry index, 0..79
    const long mol = (long)blockIdx.x * MOLS_PER_BLOCK + m;

    // Front-batch both global loads (MLP=2); they resolve under the
    // zero/barrier phases below.
    const float4 e4 = __ldcs(reinterpret_cast<const float4*>(edges) + mol * A + a);
    const int ring_atom = __ldcs(rings + mol * (R * S) + a);

    // Phase 0: each thread zeroes its own atom's staging row (STS.128).
    staging[m][a] = make_uint4(0u, 0u, 0u, 0u);
    __syncthreads();

    // Phase 1: RMW-free byte scatter. Entry a belongs to ring r = a>>3.
    if (ring_atom >= 0) {
        reinterpret_cast<char*>(&staging[m][ring_atom])[a >> 3] = 1;
    }
    __syncthreads();

    // Phase 2: collapse own staging row (one LDS.128) into a 10-bit mask via
    // movemask multiplies. Flag bytes are 0/1, so no carries.
    unsigned int my_rings;
    {
        const uint4 row = staging[m][a];
        const unsigned int M = 0x08040201u;
        const unsigned int m0 = (row.x * M) >> 24 & 0xFu;   // rings 0..3 (permuted)
        const unsigned int m1 = (row.y * M) >> 24 & 0xFu;   // rings 4..7 (permuted)
        const unsigned int m2 = (row.z * M) >> 24 & 0xFu;   // rings 8..9 (permuted)
        my_rings = m0 | (m1 << 4) | (m2 << 8);
        atom_rings[m][a] = my_rings;
    }
    __syncthreads();

    // Phase 3: resolve 4 neighbor slots per atom via shared gathers.
    const int e0 = (int)e4.x;
    const int e1 = (int)e4.y;
    const int e2 = (int)e4.z;
    const int e3 = (int)e4.w;

    float4 o;
    o.x = (e0 >= 0 && (my_rings & atom_rings[m][e0])) ? 1.0f : 0.0f;
    o.y = (e1 >= 0 && (my_rings & atom_rings[m][e1])) ? 1.0f : 0.0f;
    o.z = (e2 >= 0 && (my_rings & atom_rings[m][e2])) ? 1.0f : 0.0f;
    o.w = (e3 >= 0 && (my_rings & atom_rings[m][e3])) ? 1.0f : 0.0f;

    __stwt(reinterpret_cast<float4*>(out) + mol * A + a, o);
}

extern "C" void kernel_launch(void* const* d_in, const int* in_sizes, int n_in,
                              void* d_out, int out_size)
{
    const float* edges = (const float*)d_in[0];   // [B, A, D] float32
    const int*   rings = (const int*)d_in[1];     // [B, R, S] int32
    float* out = (float*)d_out;                   // [B, A, D, 1] float32

    const int batch = out_size / (A * D);         // 16384
    const int grid = (batch + MOLS_PER_BLOCK - 1) / MOLS_PER_BLOCK;

    find_ring_bonds_kernel<<<grid, THREADS>>>(edges, rings, out);
}